// round 8
// baseline (speedup 1.0000x reference)
#include <cuda_runtime.h>

#define TILE 64
#define NTHREADS 256
#define WARPS 8
#define ROWS_PER_WARP (TILE / WARPS)   // 8
#define PI_F 3.14159265358979323846f
#define RSQRT2 0.70710678118654752440f

__global__ __launch_bounds__(NTHREADS, 4) void qp_kernel(
    const float* __restrict__ x,       // [B,1024]
    const float* __restrict__ pre_w,   // [4,1024]
    const float* __restrict__ pre_b,   // [4]
    const float* __restrict__ qw,      // [1,4,3]
    const float* __restrict__ post_w,  // [1024,4]
    const float* __restrict__ post_b,  // [1024]
    float* __restrict__ out,           // [B,1024]
    int B)
{
    __shared__ float wsm[4][1024];     // pre_w, q-major (16KB)
    __shared__ float psm[4][1024];     // post_w SoA (16KB)
    __shared__ float pbsm[1024];       // post_b (4KB)
    __shared__ float hsm[TILE][4];     // angles (1KB)
    __shared__ float4 zsm[TILE];       // expectations (1KB)
    __shared__ float usm[4][8];        // Rot matrices
    __shared__ float prebias[4];

    const int tid  = threadIdx.x;
    const int warp = tid >> 5;
    const int lane = tid & 31;
    const int tile0 = blockIdx.x * TILE;
    const unsigned FULL = 0xffffffffu;

    // ---------------- stage weights ----------------
    for (int i = tid; i < 4096; i += NTHREADS)
        ((float*)wsm)[i] = pre_w[i];
    const float4* pwg4 = (const float4*)post_w;
    for (int j = tid; j < 1024; j += NTHREADS) {
        float4 v = pwg4[j];
        psm[0][j] = v.x; psm[1][j] = v.y; psm[2][j] = v.z; psm[3][j] = v.w;
        pbsm[j] = post_b[j];
    }
    if (tid < 4) {
        prebias[tid] = pre_b[tid];
        float phi = qw[tid * 3 + 0];
        float th  = qw[tid * 3 + 1];
        float om  = qw[tid * 3 + 2];
        float spo, cpo, spm, cpm, st, ct;
        sincosf(0.5f * (phi + om), &spo, &cpo);
        sincosf(0.5f * (phi - om), &spm, &cpm);
        sincosf(0.5f * th,         &st,  &ct);
        usm[tid][0] =  cpo * ct;  usm[tid][1] = -spo * ct;  // u00
        usm[tid][2] = -cpm * st;  usm[tid][3] = -spm * st;  // u01
        usm[tid][4] =  cpm * st;  usm[tid][5] = -spm * st;  // u10
        usm[tid][6] =  cpo * ct;  usm[tid][7] =  spo * ct;  // u11
    }
    __syncthreads();

    // ---------------- Phase 1: dots, 8 rows per warp ----------------
    {
        const int lr0 = warp * ROWS_PER_WARP;
        const int r0  = tile0 + lr0;

        const float4* xr0 = (const float4*)(x + (size_t)r0 * 1024);
        float v[32];                  // v[r*4+q]
        #pragma unroll
        for (int i = 0; i < 32; i++) v[i] = 0.0f;

        #pragma unroll
        for (int it = 0; it < 8; it++) {
            const int idx = it * 32 + lane;
            float4 w0 = ((const float4*)wsm[0])[idx];
            float4 w1 = ((const float4*)wsm[1])[idx];
            float4 w2 = ((const float4*)wsm[2])[idx];
            float4 w3 = ((const float4*)wsm[3])[idx];
            #pragma unroll
            for (int r = 0; r < 8; r++) {
                float4 xv = __ldcs(&xr0[(size_t)r * 256 + idx]);
                v[r*4+0] += xv.x*w0.x + xv.y*w0.y + xv.z*w0.z + xv.w*w0.w;
                v[r*4+1] += xv.x*w1.x + xv.y*w1.y + xv.z*w1.z + xv.w*w1.w;
                v[r*4+2] += xv.x*w2.x + xv.y*w2.y + xv.z*w2.z + xv.w*w2.w;
                v[r*4+3] += xv.x*w3.x + xv.y*w3.y + xv.z*w3.z + xv.w*w3.w;
            }
        }

        // distributing reduce: 31 shfls, lane l ends holding S[l]
        #pragma unroll
        for (int i = 0; i < 16; i++) {
            float send = (lane & 16) ? v[i] : v[i+16];
            float recv = __shfl_xor_sync(FULL, send, 16);
            v[i] = ((lane & 16) ? v[i+16] : v[i]) + recv;
        }
        #pragma unroll
        for (int i = 0; i < 8; i++) {
            float send = (lane & 8) ? v[i] : v[i+8];
            float recv = __shfl_xor_sync(FULL, send, 8);
            v[i] = ((lane & 8) ? v[i+8] : v[i]) + recv;
        }
        #pragma unroll
        for (int i = 0; i < 4; i++) {
            float send = (lane & 4) ? v[i] : v[i+4];
            float recv = __shfl_xor_sync(FULL, send, 4);
            v[i] = ((lane & 4) ? v[i+4] : v[i]) + recv;
        }
        #pragma unroll
        for (int i = 0; i < 2; i++) {
            float send = (lane & 2) ? v[i] : v[i+2];
            float recv = __shfl_xor_sync(FULL, send, 2);
            v[i] = ((lane & 2) ? v[i+2] : v[i]) + recv;
        }
        {
            float send = (lane & 1) ? v[0] : v[1];
            float recv = __shfl_xor_sync(FULL, send, 1);
            v[0] = ((lane & 1) ? v[1] : v[0]) + recv;
        }
        // lane l: S for row lr0+(l>>2), qubit l&3
        const int q = lane & 3;
        hsm[lr0 + (lane >> 2)][q] = tanhf(v[0] + prebias[q]) * PI_F;
    }
    __syncthreads();

    // ---------------- Phase 2: circuit, thread-per-row ----------------
    if (tid < TILE && (tile0 + tid) < B) {
        float4 hv = *(const float4*)hsm[tid];
        float hq[4] = {hv.x, hv.y, hv.z, hv.w};

        float vr[4][2], vi[4][2];
        #pragma unroll
        for (int qq = 0; qq < 4; qq++) {
            float f = hq[qq];
            float sa, ca; sincosf(0.5f * atanf(f), &sa, &ca);
            float A  = (ca - sa) * RSQRT2;
            float Bv = (ca + sa) * RSQRT2;
            float sb, cb; sincosf(0.5f * atanf(f * f), &sb, &cb);
            vr[qq][0] = A  * cb;  vi[qq][0] = -A  * sb;
            vr[qq][1] = Bv * cb;  vi[qq][1] =  Bv * sb;
        }
        float c2r[4], c2i[4];
        #pragma unroll
        for (int j = 0; j < 4; j++) {
            int b3 = (j >> 1) & 1, b2 = j & 1;
            c2r[j] = vr[0][b3]*vr[1][b2] - vi[0][b3]*vi[1][b2];
            c2i[j] = vr[0][b3]*vi[1][b2] + vi[0][b3]*vr[1][b2];
        }
        float c3r[8], c3i[8];
        #pragma unroll
        for (int j = 0; j < 8; j++) {
            int hi = j >> 1, b1 = j & 1;
            c3r[j] = c2r[hi]*vr[2][b1] - c2i[hi]*vi[2][b1];
            c3i[j] = c2r[hi]*vi[2][b1] + c2i[hi]*vr[2][b1];
        }
        float pr[16], pim[16];
        #pragma unroll
        for (int j = 0; j < 16; j++) {
            int hi = j >> 1, b0 = j & 1;
            pr[j]  = c3r[hi]*vr[3][b0] - c3i[hi]*vi[3][b0];
            pim[j] = c3r[hi]*vi[3][b0] + c3i[hi]*vr[3][b0];
        }
        float tr[16], ti[16];
        #pragma unroll
        for (int j = 0; j < 16; j++) {
            int xg = j;
            xg ^= (xg & 1) << 3;
            xg ^= (xg >> 1) & 1;
            xg ^= ((xg >> 2) & 1) << 1;
            xg ^= ((xg >> 3) & 1) << 2;
            tr[j] = pr[xg];
            ti[j] = pim[xg];
        }
        #pragma unroll
        for (int qq = 0; qq < 4; qq++) {
            const float u00r = usm[qq][0], u00i = usm[qq][1];
            const float u01r = usm[qq][2], u01i = usm[qq][3];
            const float u10r = usm[qq][4], u10i = usm[qq][5];
            const float u11r = usm[qq][6], u11i = usm[qq][7];
            const int mask = 8 >> qq;
            #pragma unroll
            for (int j0 = 0; j0 < 16; j0++) {
                if (j0 & mask) continue;
                const int j1 = j0 | mask;
                float ar = tr[j0], ai = ti[j0];
                float br = tr[j1], bi = ti[j1];
                tr[j0] = u00r*ar - u00i*ai + u01r*br - u01i*bi;
                ti[j0] = u00r*ai + u00i*ar + u01r*bi + u01i*br;
                tr[j1] = u10r*ar - u10i*ai + u11r*br - u11i*bi;
                ti[j1] = u10r*ai + u10i*ar + u11r*bi + u11i*br;
            }
        }
        float z0 = 0.f, z1 = 0.f, z2 = 0.f, z3 = 0.f;
        #pragma unroll
        for (int j = 0; j < 16; j++) {
            float p = tr[j]*tr[j] + ti[j]*ti[j];
            z0 += (j & 8) ? -p : p;
            z1 += (j & 4) ? -p : p;
            z2 += (j & 2) ? -p : p;
            z3 += (j & 1) ? -p : p;
        }
        zsm[tid] = make_float4(z0, z1, z2, z3);
    }
    __syncthreads();

    // ---------------- Phase 3: out = z @ post_w^T + post_b, 8 rows/warp --
    {
        const int lr0 = warp * ROWS_PER_WARP;
        const int r0  = tile0 + lr0;

        float4 zv[8];
        #pragma unroll
        for (int r = 0; r < 8; r++) zv[r] = zsm[lr0 + r];

        float4* o0 = (float4*)(out + (size_t)r0 * 1024);
        #pragma unroll
        for (int jt = 0; jt < 8; jt++) {
            const int fi = jt * 32 + lane;
            float4 w0 = ((const float4*)psm[0])[fi];
            float4 w1 = ((const float4*)psm[1])[fi];
            float4 w2 = ((const float4*)psm[2])[fi];
            float4 w3 = ((const float4*)psm[3])[fi];
            float4 bb = ((const float4*)pbsm)[fi];
            #pragma unroll
            for (int r = 0; r < 8; r++) {
                float4 o;
                o.x = bb.x + zv[r].x*w0.x + zv[r].y*w1.x + zv[r].z*w2.x + zv[r].w*w3.x;
                o.y = bb.y + zv[r].x*w0.y + zv[r].y*w1.y + zv[r].z*w2.y + zv[r].w*w3.y;
                o.z = bb.z + zv[r].x*w0.z + zv[r].y*w1.z + zv[r].z*w2.z + zv[r].w*w3.z;
                o.w = bb.w + zv[r].x*w0.w + zv[r].y*w1.w + zv[r].z*w2.w + zv[r].w*w3.w;
                __stcs(&o0[(size_t)r * 256 + fi], o);
            }
        }
    }
}

extern "C" void kernel_launch(void* const* d_in, const int* in_sizes, int n_in,
                              void* d_out, int out_size) {
    const float* x      = (const float*)d_in[0];
    const float* pre_w  = (const float*)d_in[1];
    const float* pre_b  = (const float*)d_in[2];
    const float* qw     = (const float*)d_in[3];
    const float* post_w = (const float*)d_in[4];
    const float* post_b = (const float*)d_in[5];
    float* out = (float*)d_out;

    const int B = in_sizes[0] / 1024;
    const int blocks = (B + TILE - 1) / TILE;
    qp_kernel<<<blocks, NTHREADS>>>(x, pre_w, pre_b, qw, post_w, post_b, out, B);
}

// round 12
// speedup vs baseline: 1.1782x; 1.1782x over previous
#include <cuda_runtime.h>

#define TILE 64
#define NTHREADS 128
#define WARPS 4
#define ROWS_PER_WARP (TILE / WARPS)   // 16
#define GROUPS (ROWS_PER_WARP / 8)     // 2 groups of 8 rows
#define PI_F 3.14159265358979323846f
#define RSQRT2 0.70710678118654752440f

__global__ __launch_bounds__(NTHREADS, 8) void qp_kernel(
    const float* __restrict__ x,       // [B,1024]
    const float* __restrict__ pre_w,   // [4,1024]
    const float* __restrict__ pre_b,   // [4]
    const float* __restrict__ qw,      // [1,4,3]
    const float* __restrict__ post_w,  // [1024,4]
    const float* __restrict__ post_b,  // [1024]
    float* __restrict__ out,           // [B,1024]
    int B)
{
    __shared__ float wsm[4][1024];     // pre_w, q-major (16KB)
    __shared__ float hsm[TILE][4];     // angles (1KB)
    __shared__ float4 zsm[TILE];       // expectations (1KB)
    __shared__ float usm[4][8];        // Rot matrices
    __shared__ float prebias[4];

    const int tid  = threadIdx.x;
    const int warp = tid >> 5;
    const int lane = tid & 31;
    const int tile0 = blockIdx.x * TILE;
    const unsigned FULL = 0xffffffffu;

    // ---------------- stage pre_w + gate matrices ----------------
    for (int i = tid; i < 4096; i += NTHREADS)
        ((float*)wsm)[i] = pre_w[i];
    if (tid < 4) {
        prebias[tid] = pre_b[tid];
        float phi = qw[tid * 3 + 0];
        float th  = qw[tid * 3 + 1];
        float om  = qw[tid * 3 + 2];
        float spo, cpo, spm, cpm, st, ct;
        sincosf(0.5f * (phi + om), &spo, &cpo);
        sincosf(0.5f * (phi - om), &spm, &cpm);
        sincosf(0.5f * th,         &st,  &ct);
        usm[tid][0] =  cpo * ct;  usm[tid][1] = -spo * ct;  // u00
        usm[tid][2] = -cpm * st;  usm[tid][3] = -spm * st;  // u01
        usm[tid][4] =  cpm * st;  usm[tid][5] = -spm * st;  // u10
        usm[tid][6] =  cpo * ct;  usm[tid][7] =  spo * ct;  // u11
    }
    __syncthreads();

    // ---------------- Phase 1: dots, 2 groups of 8 rows per warp ---------
    #pragma unroll 1
    for (int g = 0; g < GROUPS; g++) {
        const int lr0 = warp * ROWS_PER_WARP + g * 8;
        const int r0  = tile0 + lr0;
        if (r0 + 7 >= B) continue;

        const float4* xr0 = (const float4*)(x + (size_t)r0 * 1024);
        float v[32];                  // v[r*4+q]
        #pragma unroll
        for (int i = 0; i < 32; i++) v[i] = 0.0f;

        #pragma unroll
        for (int it = 0; it < 8; it++) {
            const int idx = it * 32 + lane;
            float4 w0 = ((const float4*)wsm[0])[idx];
            float4 w1 = ((const float4*)wsm[1])[idx];
            float4 w2 = ((const float4*)wsm[2])[idx];
            float4 w3 = ((const float4*)wsm[3])[idx];
            #pragma unroll
            for (int r = 0; r < 8; r++) {
                float4 xv = __ldcs(&xr0[(size_t)r * 256 + idx]);
                v[r*4+0] += xv.x*w0.x + xv.y*w0.y + xv.z*w0.z + xv.w*w0.w;
                v[r*4+1] += xv.x*w1.x + xv.y*w1.y + xv.z*w1.z + xv.w*w1.w;
                v[r*4+2] += xv.x*w2.x + xv.y*w2.y + xv.z*w2.z + xv.w*w2.w;
                v[r*4+3] += xv.x*w3.x + xv.y*w3.y + xv.z*w3.z + xv.w*w3.w;
            }
        }

        // distributing reduce: 31 shfls, lane l ends holding S[l]
        #pragma unroll
        for (int i = 0; i < 16; i++) {
            float send = (lane & 16) ? v[i] : v[i+16];
            float recv = __shfl_xor_sync(FULL, send, 16);
            v[i] = ((lane & 16) ? v[i+16] : v[i]) + recv;
        }
        #pragma unroll
        for (int i = 0; i < 8; i++) {
            float send = (lane & 8) ? v[i] : v[i+8];
            float recv = __shfl_xor_sync(FULL, send, 8);
            v[i] = ((lane & 8) ? v[i+8] : v[i]) + recv;
        }
        #pragma unroll
        for (int i = 0; i < 4; i++) {
            float send = (lane & 4) ? v[i] : v[i+4];
            float recv = __shfl_xor_sync(FULL, send, 4);
            v[i] = ((lane & 4) ? v[i+4] : v[i]) + recv;
        }
        #pragma unroll
        for (int i = 0; i < 2; i++) {
            float send = (lane & 2) ? v[i] : v[i+2];
            float recv = __shfl_xor_sync(FULL, send, 2);
            v[i] = ((lane & 2) ? v[i+2] : v[i]) + recv;
        }
        {
            float send = (lane & 1) ? v[0] : v[1];
            float recv = __shfl_xor_sync(FULL, send, 1);
            v[0] = ((lane & 1) ? v[1] : v[0]) + recv;
        }
        // lane l: S for row lr0+(l>>2), qubit l&3
        const int q = lane & 3;
        hsm[lr0 + (lane >> 2)][q] = tanhf(v[0] + prebias[q]) * PI_F;
    }
    __syncthreads();

    // ---------------- Phase 2: circuit, thread-per-row ----------------
    if (tid < TILE && (tile0 + tid) < B) {
        float4 hv = *(const float4*)hsm[tid];
        float hq[4] = {hv.x, hv.y, hv.z, hv.w};

        float vr[4][2], vi[4][2];
        #pragma unroll
        for (int qq = 0; qq < 4; qq++) {
            float f = hq[qq];
            float sa, ca; sincosf(0.5f * atanf(f), &sa, &ca);
            float A  = (ca - sa) * RSQRT2;
            float Bv = (ca + sa) * RSQRT2;
            float sb, cb; sincosf(0.5f * atanf(f * f), &sb, &cb);
            vr[qq][0] = A  * cb;  vi[qq][0] = -A  * sb;
            vr[qq][1] = Bv * cb;  vi[qq][1] =  Bv * sb;
        }
        float c2r[4], c2i[4];
        #pragma unroll
        for (int j = 0; j < 4; j++) {
            int b3 = (j >> 1) & 1, b2 = j & 1;
            c2r[j] = vr[0][b3]*vr[1][b2] - vi[0][b3]*vi[1][b2];
            c2i[j] = vr[0][b3]*vi[1][b2] + vi[0][b3]*vr[1][b2];
        }
        float c3r[8], c3i[8];
        #pragma unroll
        for (int j = 0; j < 8; j++) {
            int hi = j >> 1, b1 = j & 1;
            c3r[j] = c2r[hi]*vr[2][b1] - c2i[hi]*vi[2][b1];
            c3i[j] = c2r[hi]*vi[2][b1] + c2i[hi]*vr[2][b1];
        }
        float pr[16], pim[16];
        #pragma unroll
        for (int j = 0; j < 16; j++) {
            int hi = j >> 1, b0 = j & 1;
            pr[j]  = c3r[hi]*vr[3][b0] - c3i[hi]*vi[3][b0];
            pim[j] = c3r[hi]*vi[3][b0] + c3i[hi]*vr[3][b0];
        }
        float tr[16], ti[16];
        #pragma unroll
        for (int j = 0; j < 16; j++) {
            int xg = j;
            xg ^= (xg & 1) << 3;
            xg ^= (xg >> 1) & 1;
            xg ^= ((xg >> 2) & 1) << 1;
            xg ^= ((xg >> 3) & 1) << 2;
            tr[j] = pr[xg];
            ti[j] = pim[xg];
        }
        #pragma unroll
        for (int qq = 0; qq < 4; qq++) {
            const float u00r = usm[qq][0], u00i = usm[qq][1];
            const float u01r = usm[qq][2], u01i = usm[qq][3];
            const float u10r = usm[qq][4], u10i = usm[qq][5];
            const float u11r = usm[qq][6], u11i = usm[qq][7];
            const int mask = 8 >> qq;
            #pragma unroll
            for (int j0 = 0; j0 < 16; j0++) {
                if (j0 & mask) continue;
                const int j1 = j0 | mask;
                float ar = tr[j0], ai = ti[j0];
                float br = tr[j1], bi = ti[j1];
                tr[j0] = u00r*ar - u00i*ai + u01r*br - u01i*bi;
                ti[j0] = u00r*ai + u00i*ar + u01r*bi + u01i*br;
                tr[j1] = u10r*ar - u10i*ai + u11r*br - u11i*bi;
                ti[j1] = u10r*ai + u10i*ar + u11r*bi + u11i*br;
            }
        }
        float z0 = 0.f, z1 = 0.f, z2 = 0.f, z3 = 0.f;
        #pragma unroll
        for (int j = 0; j < 16; j++) {
            float p = tr[j]*tr[j] + ti[j]*ti[j];
            z0 += (j & 8) ? -p : p;
            z1 += (j & 4) ? -p : p;
            z2 += (j & 2) ? -p : p;
            z3 += (j & 1) ? -p : p;
        }
        zsm[tid] = make_float4(z0, z1, z2, z3);
    }
    __syncthreads();

    // ---------------- Phase 3: out = z @ post_w^T + post_b ---------------
    // post_w/post_b read directly via __ldg (20KB, L1-resident, shared by
    // all resident blocks on the SM).
    const float4* pwg4 = (const float4*)post_w;   // pwg4[j] = w[j][0..3]
    const float4* pbg4 = (const float4*)post_b;
    #pragma unroll 1
    for (int g = 0; g < GROUPS; g++) {
        const int lr0 = warp * ROWS_PER_WARP + g * 8;
        const int r0  = tile0 + lr0;
        if (r0 + 7 >= B) continue;

        float4 zv[8];
        #pragma unroll
        for (int r = 0; r < 8; r++) zv[r] = zsm[lr0 + r];

        float4* o0 = (float4*)(out + (size_t)r0 * 1024);
        #pragma unroll
        for (int jt = 0; jt < 8; jt++) {
            const int fi = jt * 32 + lane;       // float4 index, cols 4fi..4fi+3
            float4 g0 = __ldg(&pwg4[4*fi + 0]);  // weights for col 4fi+0
            float4 g1 = __ldg(&pwg4[4*fi + 1]);
            float4 g2 = __ldg(&pwg4[4*fi + 2]);
            float4 g3 = __ldg(&pwg4[4*fi + 3]);
            float4 bb = __ldg(&pbg4[fi]);
            #pragma unroll
            for (int r = 0; r < 8; r++) {
                float4 o;
                o.x = bb.x + zv[r].x*g0.x + zv[r].y*g0.y + zv[r].z*g0.z + zv[r].w*g0.w;
                o.y = bb.y + zv[r].x*g1.x + zv[r].y*g1.y + zv[r].z*g1.z + zv[r].w*g1.w;
                o.z = bb.z + zv[r].x*g2.x + zv[r].y*g2.y + zv[r].z*g2.z + zv[r].w*g2.w;
                o.w = bb.w + zv[r].x*g3.x + zv[r].y*g3.y + zv[r].z*g3.z + zv[r].w*g3.w;
                __stcs(&o0[(size_t)r * 256 + fi], o);
            }
        }
    }
}

extern "C" void kernel_launch(void* const* d_in, const int* in_sizes, int n_in,
                              void* d_out, int out_size) {
    const float* x      = (const float*)d_in[0];
    const float* pre_w  = (const float*)d_in[1];
    const float* pre_b  = (const float*)d_in[2];
    const float* qw     = (const float*)d_in[3];
    const float* post_w = (const float*)d_in[4];
    const float* post_b = (const float*)d_in[5];
    float* out = (float*)d_out;

    const int B = in_sizes[0] / 1024;
    const int blocks = (B + TILE - 1) / TILE;
    qp_kernel<<<blocks, NTHREADS>>>(x, pre_w, pre_b, qw, post_w, post_b, out, B);
}